// round 12
// baseline (speedup 1.0000x reference)
#include <cuda_runtime.h>
#include <math_constants.h>
#include <cstdint>

#define BB 128
#define TT 2048
#define HH 256
#define OUTD 128

#define NCHUNK 8                          // chunks per batch
#define ROWS_PER_CTA (TT / NCHUNK)        // 256 rows
#define NPART (BB * NCHUNK)               // 1024

#define K1_THREADS 128                    // 4 warps
#define K1_WARPS 4
#define ROWS_PER_WARP (ROWS_PER_CTA / K1_WARPS)   // 64
#define STAGE_ROWS 4
#define STAGE_BYTES (STAGE_ROWS * HH * 4) // 4096
#define NSTAGE 4
#define ITERS (ROWS_PER_WARP / STAGE_ROWS) // 16

#define NVCTA 256                         // CTAs that also compute v tiles

// dynamic smem layout (bytes)
#define OFF_TILES 0
#define SZ_TILES  (K1_WARPS * NSTAGE * STAGE_BYTES)    // 65536
#define OFF_ACC   (OFF_TILES + SZ_TILES)               // 65536
#define SZ_ACC    (K1_WARPS * HH * 4)                  // 4096
#define OFF_WM    (OFF_ACC + SZ_ACC)                   // 69632
#define OFF_WZ    (OFF_WM + 16)
#define OFF_BARS  (OFF_WZ + 16)                        // 69664 (8-aligned)
#define SMEM_K1   (OFF_BARS + K1_WARPS * NSTAGE * 8)   // 69792 -> 3 CTAs/SM

// Global scratch (allocation-free)
__device__ float g_v[BB * HH];
__device__ float g_m[NPART];
__device__ float g_z[NPART];
__device__ float g_acc[NPART * HH];
__device__ unsigned int g_flag = 0;       // v-ready counter; reset by k2

// ---------------- PTX helpers ----------------
__device__ __forceinline__ uint32_t s2u(const void* p) {
    uint32_t a;
    asm("{ .reg .u64 t; cvta.to.shared.u64 t, %1; cvt.u32.u64 %0, t; }"
        : "=r"(a) : "l"(p));
    return a;
}
__device__ __forceinline__ void mbar_init(uint32_t bar, uint32_t cnt) {
    asm volatile("mbarrier.init.shared.b64 [%0], %1;" :: "r"(bar), "r"(cnt) : "memory");
}
__device__ __forceinline__ void mbar_expect_tx(uint32_t bar, uint32_t bytes) {
    asm volatile("mbarrier.arrive.expect_tx.shared.b64 _, [%0], %1;"
                 :: "r"(bar), "r"(bytes) : "memory");
}
__device__ __forceinline__ void mbar_wait(uint32_t bar, uint32_t parity) {
    uint32_t done;
    asm volatile(
        "{ .reg .pred p; mbarrier.try_wait.parity.acquire.cta.shared::cta.b64 p, [%1], %2; "
        "selp.b32 %0, 1, 0, p; }" : "=r"(done) : "r"(bar), "r"(parity) : "memory");
    while (!done) {
        asm volatile(
            "{ .reg .pred p; mbarrier.try_wait.parity.acquire.cta.shared::cta.b64 p, [%1], %2, 0x989680; "
            "selp.b32 %0, 1, 0, p; }" : "=r"(done) : "r"(bar), "r"(parity) : "memory");
    }
}
__device__ __forceinline__ void bulk_copy_g2s(uint32_t dst_smem, const void* src,
                                              uint32_t bytes, uint32_t mbar) {
    asm volatile(
        "cp.async.bulk.shared::cta.global.mbarrier::complete_tx::bytes [%0], [%1], %2, [%3];"
        :: "r"(dst_smem), "l"(src), "r"(bytes), "r"(mbar) : "memory");
}
__device__ __forceinline__ void fence_async_shared() {
    asm volatile("fence.proxy.async.shared::cta;" ::: "memory");
}
__device__ __forceinline__ void pdl_wait() {
    asm volatile("griddepcontrol.wait;" ::: "memory");
}
__device__ __forceinline__ void pdl_launch_dependents() {
    asm volatile("griddepcontrol.launch_dependents;" ::: "memory");
}
__device__ __forceinline__ unsigned int ld_acquire_gpu(const unsigned int* p) {
    unsigned int v;
    asm volatile("ld.acquire.gpu.global.u32 %0, [%1];" : "=r"(v) : "l"(p) : "memory");
    return v;
}
__device__ __forceinline__ void red_release_add(unsigned int* p, unsigned int v) {
    asm volatile("red.release.gpu.global.add.u32 [%0], %1;" :: "l"(p), "r"(v) : "memory");
}

// ---------------------------------------------------------------------------
// kernel1: fused v-compute + per-warp self-paced bulk-async streaming.
//   grid = 1024 CTAs x 128 thr, 3 CTAs/SM.
//   CTAs 0..255 compute an 8b x 16h tile of v = W_score @ h_t after issuing
//   their prologue copies, then release g_flag. All CTAs spin on g_flag==256
//   (acquire) before reading g_v. v-computers are all inside wave 1 (444
//   slots), so no deadlock. g_flag is reset by k2 each launch.
// ---------------------------------------------------------------------------
__global__ __launch_bounds__(K1_THREADS, 3)
void k1_stream(const float* __restrict__ hidden,
               const float* __restrict__ Wscore)
{
    extern __shared__ __align__(128) unsigned char smem_raw[];
    float* s_tiles = (float*)(smem_raw + OFF_TILES);
    float* s_acc   = (float*)(smem_raw + OFF_ACC);
    float* s_wm    = (float*)(smem_raw + OFF_WM);
    float* s_wz    = (float*)(smem_raw + OFF_WZ);

    const int cta   = blockIdx.x;
    const int b     = cta >> 3;               // / NCHUNK
    const int chunk = cta & (NCHUNK - 1);
    const int tid   = threadIdx.x, w = tid >> 5, lane = tid & 31;

    const uint32_t bar0  = s2u(smem_raw + OFF_BARS) + w * NSTAGE * 8;
    const uint32_t tile0 = s2u(smem_raw) + w * NSTAGE * STAGE_BYTES;
    float* tbase = s_tiles + w * NSTAGE * (STAGE_ROWS * HH);

    const float* src = hidden
        + ((size_t)b * TT + chunk * ROWS_PER_CTA + w * ROWS_PER_WARP) * HH;

    // per-warp barrier init + prologue copies -- issued FIRST so the memory
    // system is busy while v is computed
    if (lane == 0) {
        #pragma unroll
        for (int s = 0; s < NSTAGE; s++) mbar_init(bar0 + s * 8, 1);
        fence_async_shared();
        #pragma unroll
        for (int s = 0; s < NSTAGE; s++) {
            mbar_expect_tx(bar0 + s * 8, STAGE_BYTES);
            bulk_copy_g2s(tile0 + s * STAGE_BYTES,
                          src + (size_t)s * STAGE_ROWS * HH,
                          STAGE_BYTES, bar0 + s * 8);
        }
    }
    __syncwarp();

    // ---- v-compute for CTAs 0..255: tile = 8 batches x 16 h-rows ----
    if (cta < NVCTA) {
        const int vb0 = (cta & 15) * 8;           // 8 batches
        const int vh0 = (cta >> 4) * 16 + w * 4;  // warp: 4 h-rows

        const float* wp = Wscore + (size_t)vh0 * HH;
        float4 W0[4], W1[4];
        #pragma unroll
        for (int r = 0; r < 4; r++) {
            W0[r] = *(const float4*)(wp + (size_t)r * HH + lane * 4);
            W1[r] = *(const float4*)(wp + (size_t)r * HH + 128 + lane * 4);
        }
        // prefetch first ht row
        const float* hp = hidden + ((size_t)vb0 * TT + (TT - 1)) * HH;
        float4 x0 = *(const float4*)(hp + lane * 4);
        float4 x1 = *(const float4*)(hp + 128 + lane * 4);

        #pragma unroll
        for (int bb = 0; bb < 8; bb++) {
            float4 n0, n1;
            if (bb < 7) {
                const float* np = hidden + ((size_t)(vb0 + bb + 1) * TT + (TT - 1)) * HH;
                n0 = *(const float4*)(np + lane * 4);
                n1 = *(const float4*)(np + 128 + lane * 4);
            }
            float s0 = W0[0].x*x0.x + W0[0].y*x0.y + W0[0].z*x0.z + W0[0].w*x0.w
                     + W1[0].x*x1.x + W1[0].y*x1.y + W1[0].z*x1.z + W1[0].w*x1.w;
            float s1 = W0[1].x*x0.x + W0[1].y*x0.y + W0[1].z*x0.z + W0[1].w*x0.w
                     + W1[1].x*x1.x + W1[1].y*x1.y + W1[1].z*x1.z + W1[1].w*x1.w;
            float s2 = W0[2].x*x0.x + W0[2].y*x0.y + W0[2].z*x0.z + W0[2].w*x0.w
                     + W1[2].x*x1.x + W1[2].y*x1.y + W1[2].z*x1.z + W1[2].w*x1.w;
            float s3 = W0[3].x*x0.x + W0[3].y*x0.y + W0[3].z*x0.z + W0[3].w*x0.w
                     + W1[3].x*x1.x + W1[3].y*x1.y + W1[3].z*x1.z + W1[3].w*x1.w;
            #pragma unroll
            for (int off = 16; off; off >>= 1) {
                s0 += __shfl_xor_sync(0xffffffffu, s0, off);
                s1 += __shfl_xor_sync(0xffffffffu, s1, off);
                s2 += __shfl_xor_sync(0xffffffffu, s2, off);
                s3 += __shfl_xor_sync(0xffffffffu, s3, off);
            }
            const float val = (lane == 0) ? s0 : (lane == 1) ? s1
                            : (lane == 2) ? s2 : s3;
            if (lane < 4)
                g_v[(vb0 + bb) * HH + vh0 + lane] = val;
            x0 = n0; x1 = n1;
        }
        __syncthreads();                  // all warps' g_v stores issued
        if (tid == 0) {
            __threadfence();
            red_release_add(&g_flag, 1);
        }
    }

    // ---- all CTAs: wait for full v, then load this batch's slice ----
    if (tid == 0) {
        while (ld_acquire_gpu(&g_flag) < NVCTA) __nanosleep(100);
    }
    __syncthreads();

    const float4 v0 = *(const float4*)(g_v + b * HH + lane * 4);
    const float4 v1 = *(const float4*)(g_v + b * HH + 128 + lane * 4);

    float  m = -CUDART_INF_F, Z = 0.f;
    float4 a0 = make_float4(0.f, 0.f, 0.f, 0.f);
    float4 a1 = make_float4(0.f, 0.f, 0.f, 0.f);

    for (int i = 0; i < ITERS; i++) {
        const int s = i & (NSTAGE - 1);
        mbar_wait(bar0 + s * 8, (i >> 2) & 1);

        const float* tp = tbase + s * (STAGE_ROWS * HH);
        float4 x[STAGE_ROWS][2];
        #pragma unroll
        for (int r = 0; r < STAGE_ROWS; r++) {
            x[r][0] = *(const float4*)(tp + r * HH + lane * 4);
            x[r][1] = *(const float4*)(tp + r * HH + 128 + lane * 4);
        }

        // consume the registers first (score FMAs)...
        float sc[STAGE_ROWS];
        #pragma unroll
        for (int r = 0; r < STAGE_ROWS; r++) {
            sc[r] = x[r][0].x * v0.x + x[r][0].y * v0.y + x[r][0].z * v0.z + x[r][0].w * v0.w
                  + x[r][1].x * v1.x + x[r][1].y * v1.y + x[r][1].z * v1.z + x[r][1].w * v1.w;
        }

        // ...then refill stage s (all lanes' LDS done per __syncwarp)
        __syncwarp();
        if (lane == 0 && i + NSTAGE < ITERS) {
            mbar_expect_tx(bar0 + s * 8, STAGE_BYTES);
            bulk_copy_g2s(tile0 + s * STAGE_BYTES,
                          src + (size_t)(i + NSTAGE) * STAGE_ROWS * HH,
                          STAGE_BYTES, bar0 + s * 8);
        }

        #pragma unroll
        for (int off = 16; off; off >>= 1) {
            #pragma unroll
            for (int r = 0; r < STAGE_ROWS; r++)
                sc[r] += __shfl_xor_sync(0xffffffffu, sc[r], off);
        }
        const float mc = fmaxf(fmaxf(sc[0], sc[1]), fmaxf(sc[2], sc[3]));
        if (mc > m) {                          // warp-uniform
            const float rr = __expf(m - mc);   // first stage: exp(-inf)=0
            Z *= rr;
            a0.x *= rr; a0.y *= rr; a0.z *= rr; a0.w *= rr;
            a1.x *= rr; a1.y *= rr; a1.z *= rr; a1.w *= rr;
            m = mc;
        }
        #pragma unroll
        for (int r = 0; r < STAGE_ROWS; r++) {
            const float p = __expf(sc[r] - m);
            Z += p;
            a0.x += p * x[r][0].x; a0.y += p * x[r][0].y;
            a0.z += p * x[r][0].z; a0.w += p * x[r][0].w;
            a1.x += p * x[r][1].x; a1.y += p * x[r][1].y;
            a1.z += p * x[r][1].z; a1.w += p * x[r][1].w;
        }
    }

    // intra-CTA combine (4 warps)
    if (lane == 0) { s_wm[w] = m; s_wz[w] = Z; }
    *(float4*)(&s_acc[w * HH + lane * 4])       = a0;
    *(float4*)(&s_acc[w * HH + 128 + lane * 4]) = a1;
    __syncthreads();

    const float M = fmaxf(fmaxf(s_wm[0], s_wm[1]), fmaxf(s_wm[2], s_wm[3]));
    const float e0 = __expf(s_wm[0] - M), e1 = __expf(s_wm[1] - M);
    const float e2 = __expf(s_wm[2] - M), e3 = __expf(s_wm[3] - M);

    if (tid == 0) {
        g_m[cta] = M;
        g_z[cta] = e0 * s_wz[0] + e1 * s_wz[1] + e2 * s_wz[2] + e3 * s_wz[3];
    }
    #pragma unroll
    for (int jj = 0; jj < 2; jj++) {
        const int ch = tid + jj * 128;
        g_acc[(size_t)cta * HH + ch] =
            e0 * s_acc[0 * HH + ch] + e1 * s_acc[1 * HH + ch]
          + e2 * s_acc[2 * HH + ch] + e3 * s_acc[3 * HH + ch];
    }
    pdl_launch_dependents();
}

// ---------------------------------------------------------------------------
// kernel2: merge partials -> ctx; out = tanh(concat(ctx,h_t) @ W_att).
//          grid = 16 CTAs x 8 batches, 512 thr. Also resets g_flag.
// ---------------------------------------------------------------------------
__global__ __launch_bounds__(512)
void k2_combine(const float* __restrict__ hidden,
                const float* __restrict__ Watt,
                float* __restrict__ out)
{
    __shared__ float s_pre[8][2 * HH];   // 16KB
    __shared__ float s_e[8][NCHUNK];
    __shared__ float s_Z[8];
    __shared__ float sW[32 * OUTD];      // 16KB W_att tile

    const int b0 = blockIdx.x * 8;
    const int tid = threadIdx.x;

    pdl_wait();                          // k1 fully done (incl. all flag use)

    if (tid == 0) g_flag = 0;            // reset for next graph replay

    if (tid < 8 * NCHUNK) {              // stash m values
        const int bi = tid >> 3, p = tid & 7;
        s_e[bi][p] = g_m[(b0 + bi) * NCHUNK + p];
    }
    __syncthreads();
    if (tid < 8) {
        float M = -CUDART_INF_F;
        #pragma unroll
        for (int p = 0; p < NCHUNK; p++) M = fmaxf(M, s_e[tid][p]);
        float Zt = 0.f;
        #pragma unroll
        for (int p = 0; p < NCHUNK; p++) {
            const float e = __expf(s_e[tid][p] - M);
            Zt += e * g_z[(b0 + tid) * NCHUNK + p];
            s_e[tid][p] = e;
        }
        s_Z[tid] = Zt;
    }
    __syncthreads();

    const int bi = tid >> 6, c0 = tid & 63;
    #pragma unroll
    for (int cc = 0; cc < 4; cc++) {
        const int ch = c0 + cc * 64;
        float c = 0.f;
        #pragma unroll
        for (int p = 0; p < NCHUNK; p++)
            c += s_e[bi][p] * g_acc[(size_t)((b0 + bi) * NCHUNK + p) * HH + ch];
        s_pre[bi][ch]      = c / s_Z[bi];
        s_pre[bi][HH + ch] = hidden[((size_t)(b0 + bi) * TT + (TT - 1)) * HH + ch];
    }
    __syncthreads();

    // out[bi][j], 2 outputs per thread; W_att tiled 32 rows at a time via smem
    const int j = tid & 63;
    float acc0 = 0.f, acc1 = 0.f;
    for (int t = 0; t < 16; t++) {
        #pragma unroll
        for (int q = 0; q < 8; q++)      // 512 thr load 32x128 = 4096 floats
            sW[tid + q * 512] = Watt[(t * 32) * OUTD + tid + q * 512];
        __syncthreads();
        #pragma unroll
        for (int i = 0; i < 32; i++) {
            const float p = s_pre[bi][t * 32 + i];
            acc0 += p * sW[i * OUTD + j];
            acc1 += p * sW[i * OUTD + j + 64];
        }
        __syncthreads();
    }
    out[(b0 + bi) * OUTD + j]      = tanhf(acc0);
    out[(b0 + bi) * OUTD + j + 64] = tanhf(acc1);
}

extern "C" void kernel_launch(void* const* d_in, const int* in_sizes, int n_in,
                              void* d_out, int out_size) {
    const float* hidden = (const float*)d_in[0];   // (128, 2048, 256) f32
    const float* Wscore = (const float*)d_in[1];   // (256, 256) f32
    const float* Watt   = (const float*)d_in[2];   // (512, 128) f32
    float* out = (float*)d_out;                    // (128, 128) f32

    cudaFuncSetAttribute(k1_stream, cudaFuncAttributeMaxDynamicSharedMemorySize, SMEM_K1);

    k1_stream<<<BB * NCHUNK, K1_THREADS, SMEM_K1>>>(hidden, Wscore);

    cudaLaunchAttribute pdl_attr;
    pdl_attr.id = cudaLaunchAttributeProgrammaticStreamSerialization;
    pdl_attr.val.programmaticStreamSerializationAllowed = 1;

    {   // k2 with PDL
        cudaLaunchConfig_t cfg = {};
        cfg.gridDim = dim3(16);
        cfg.blockDim = dim3(512);
        cfg.dynamicSmemBytes = 0;
        cfg.stream = 0;
        cfg.attrs = &pdl_attr;
        cfg.numAttrs = 1;
        cudaLaunchKernelEx(&cfg, k2_combine, hidden, Watt, out);
    }
}